// round 13
// baseline (speedup 1.0000x reference)
#include <cuda_runtime.h>
#include <cuda_bf16.h>
#include <math.h>

// Problem constants
#define TT     1024
#define DD     4
#define PP     8
#define DPW    32                    // D*P
#define SS     256                   // N * N_SAMPLE
#define LT     16                    // timesteps per P1 chunk (deep MLP)
#define NCHUNK 64                    // 16-chunks along T
#define QTR    4                     // blocks per sample
#define TBL    (TT*DPW)              // 32768 table elements
#define SZ     ((size_t)SS*TT*DPW)   // 8388608 elements per output tensor
#define HLOG2PI 0.91893853320467274178f

// Scratch (static __device__ arrays — allocation-free)
__device__ float  g_mean[TBL];
__device__ float  g_sw[TBL];
__device__ float  g_amul[TT*DD];          // sigmoid(a_raw[t-1,d]), amul[0,*]=0
__device__ float  g_Q[TT*DD];             // within-16-chunk prefix products of amul
__device__ float4 g_B[SS*NCHUNK*8];       // per-chunk local end values, 2 MB
__device__ float4 g_C[SS*NCHUNK*8];       // exclusive carries, 2 MB

// ---------------------------------------------------------------------------
// K0: precompute per-(t,dp) tables. Fast-math; tiny.
// ---------------------------------------------------------------------------
__global__ void arma_precompute(const float* __restrict__ m,
                                const float* __restrict__ s_raw,
                                const float* __restrict__ a_raw,
                                const int*   __restrict__ dim_idx)
{
    int idx = blockIdx.x * blockDim.x + threadIdx.x;
    if (idx >= TBL) return;
    int t  = idx >> 5;
    int dp = idx & 31;
    int dd = dp >> 3;
    int p  = dp & 7;
    int src = dim_idx[dd];

    float am = 0.0f;
    if (t > 0) {
        float x = a_raw[(t - 1) * DD + src];
        am = 1.0f / (1.0f + __expf(-x));
    }

    float sv = s_raw[t * DPW + src * PP + p];
    float sw = (sv > 20.0f) ? sv : __logf(1.0f + __expf(sv));   // softplus
    float mn = (1.0f - am) * m[t * DPW + src * PP + p];

    g_mean[idx] = mn;
    g_sw[idx]   = sw;
    if (p == 0) g_amul[t * DD + dd] = am;
}

// ---------------------------------------------------------------------------
// K0b: Q table — within-16-chunk prefix products of amul.
// Q[t,d] = prod_{j = 16*floor(t/16) .. t} amul[j,d].  4096 threads, trivial.
// ---------------------------------------------------------------------------
__global__ void arma_qtab()
{
    int idx = blockIdx.x * blockDim.x + threadIdx.x;   // 0..4095
    if (idx >= TT * DD) return;
    int t  = idx >> 2;
    int dd = idx & 3;
    int t0 = t & ~15;
    float qv = 1.0f;
    for (int j = t0; j <= t; j++)
        qv *= g_amul[(j << 2) + dd];
    g_Q[idx] = qv;
}

// ---------------------------------------------------------------------------
// P1: stream noise once (float4, DEFAULT policy), write lp (__stcs), store
// running LOCAL values into param (default policy -> L2; overwritten by P3),
// emit per-16-chunk summaries b (= local at chunk end).
// Grid: 1024 blocks x 128 threads (16 chunks x 8 quads, LT=16 for deep MLP).
// ---------------------------------------------------------------------------
__global__ void __launch_bounds__(128)
arma_pass1(const float4* __restrict__ noise4,
           float4* __restrict__ param4,
           float4* __restrict__ lp4,
           int write_lp)
{
    const int s     = blockIdx.x >> 2;
    const int qt    = blockIdx.x & 3;
    const int q     = threadIdx.x & 7;                  // dp quad: dp = 4q..4q+3
    const int chunk = (qt << 4) + (threadIdx.x >> 3);   // 0..63
    const int dd    = q >> 1;
    const int t0    = chunk << 4;

    const float4* tbl_sw = (const float4*)g_sw;
    const float4* tbl_mn = (const float4*)g_mean;

    const size_t base = ((size_t)((s << 10) + t0) << 3) + q;   // float4 index

    float4 b = make_float4(0.f, 0.f, 0.f, 0.f);

#pragma unroll
    for (int i = 0; i < LT; i++) {
        const int t  = t0 + i;
        const int ti = (t << 3) + q;
        const float4 n = noise4[base + (size_t)i * 8];
        const float4 sw = tbl_sw[ti];
        const float4 mn = tbl_mn[ti];
        if (write_lp) {
            float4 lp;
            lp.x = fmaf(-0.5f * n.x, n.x, -__logf(sw.x) - HLOG2PI);
            lp.y = fmaf(-0.5f * n.y, n.y, -__logf(sw.y) - HLOG2PI);
            lp.z = fmaf(-0.5f * n.z, n.z, -__logf(sw.z) - HLOG2PI);
            lp.w = fmaf(-0.5f * n.w, n.w, -__logf(sw.w) - HLOG2PI);
            __stcs(&lp4[base + (size_t)i * 8], lp);
        }
        const float am = g_amul[(t << 2) + dd];
        b.x = fmaf(am, b.x, fmaf(sw.x, n.x, mn.x));
        b.y = fmaf(am, b.y, fmaf(sw.y, n.y, mn.y));
        b.z = fmaf(am, b.z, fmaf(sw.z, n.z, mn.z));
        b.w = fmaf(am, b.w, fmaf(sw.w, n.w, mn.w));
        param4[base + (size_t)i * 8] = b;   // local value; stays in L2 for P3
    }
    g_B[(((size_t)s << 6) + chunk) * 8 + q] = b;
}

// ---------------------------------------------------------------------------
// P2: per-sample scan entirely in shared memory (R10's winner, unchanged).
// ---------------------------------------------------------------------------
__global__ void __launch_bounds__(256)
arma_scan()
{
    const int s   = blockIdx.x;
    const int tid = threadIdx.x;

    __shared__ float s_am[TT * DD];       // 16 KB
    __shared__ float sA[NCHUNK][DD];      // 1 KB
    __shared__ float sB[NCHUNK][DPW];     // 8 KB

#pragma unroll
    for (int k = 0; k < 4; k++)
        ((float4*)s_am)[tid + 256 * k] = ((const float4*)g_amul)[tid + 256 * k];

    const float4* Bs = g_B + ((size_t)s << 6) * 8;
    ((float4*)sB)[tid]       = Bs[tid];
    ((float4*)sB)[tid + 256] = Bs[tid + 256];
    __syncthreads();

    {
        const int c  = tid >> 2;
        const int d2 = tid & 3;
        float a = 1.0f;
#pragma unroll
        for (int i = 0; i < LT; i++)
            a *= s_am[(((c << 4) + i) << 2) + d2];
        sA[c][d2] = a;
    }
    __syncthreads();

    if (tid < 32) {
        const int dp = tid;
        const int d2 = dp >> 3;
        float* Cf = (float*)g_C + ((size_t)s << 6) * 32;
        float carry = 0.0f;
#pragma unroll
        for (int c = 0; c < NCHUNK; c++) {
            Cf[c * 32 + dp] = carry;                       // coalesced 128B
            carry = fmaf(sA[c][d2], carry, sB[c][dp]);
        }
    }
}

// ---------------------------------------------------------------------------
// P3-light: final(t) = local(t) + Q(t)*C16.  No noise, no sw/mn tables.
// Locals come from param (L2 hit, written by P1); Q is a hot 16KB table;
// C16 is one float4 per thread. LT=8 -> 262144 threads = 86% of chip thread
// slots (this was the R11 lever that took P3 to 12.4us, now with 1/2 traffic).
// Grid: 1024 blocks (s, quarter) x 256 threads (32 8-chunks x 8 quads).
// ---------------------------------------------------------------------------
__global__ void __launch_bounds__(256)
arma_pass3(float4* __restrict__ param4)
{
    const int s      = blockIdx.x >> 2;
    const int qt     = blockIdx.x & 3;
    const int q      = threadIdx.x & 7;
    const int chunk8 = (qt << 5) + (threadIdx.x >> 3);   // 0..127
    const int dd     = q >> 1;
    const int t0     = chunk8 << 3;
    const int chunk16 = chunk8 >> 1;

    const size_t base = ((size_t)((s << 10) + t0) << 3) + q;

    const float4 c16 = g_C[(((size_t)s << 6) + chunk16) * 8 + q];

#pragma unroll
    for (int i = 0; i < LT / 2; i++) {
        const int t = t0 + i;
        const float Qv = g_Q[(t << 2) + dd];             // hot 16KB table
        const float4 lv = param4[base + (size_t)i * 8];  // L2 hit (P1 local)
        float4 outv;
        outv.x = fmaf(Qv, c16.x, lv.x);
        outv.y = fmaf(Qv, c16.y, lv.y);
        outv.z = fmaf(Qv, c16.z, lv.z);
        outv.w = fmaf(Qv, c16.w, lv.w);
        __stcs(&param4[base + (size_t)i * 8], outv);
    }
}

// ---------------------------------------------------------------------------
// Launch.  Inputs: 0:y 1:age 2:m 3:s_raw 4:a_raw 5:noise 6:cond_sample
//                  7:dim_idx 8:compute_log_prob
// Output: param (S,T,D,P) then log_prob (S,T,D,P), float32.
// ---------------------------------------------------------------------------
extern "C" void kernel_launch(void* const* d_in, const int* in_sizes, int n_in,
                              void* d_out, int out_size)
{
    const float* m      = (const float*)d_in[2];
    const float* s_raw  = (const float*)d_in[3];
    const float* a_raw  = (const float*)d_in[4];
    const float* noise  = (const float*)d_in[5];
    const int*   dimidx = (const int*)  d_in[7];

    float* out_param = (float*)d_out;
    int write_lp = (out_size >= (int)(2 * SZ)) ? 1 : 0;
    float* out_lp = out_param + SZ;

    const float4* noise4 = (const float4*)noise;
    float4* param4 = (float4*)out_param;
    float4* lp4    = (float4*)(write_lp ? out_lp : out_param);

    arma_precompute<<<256, 128>>>(m, s_raw, a_raw, dimidx);
    arma_qtab<<<16, 256>>>();
    arma_pass1<<<SS * QTR, 128>>>(noise4, param4, lp4, write_lp);
    arma_scan<<<SS, 256>>>();
    arma_pass3<<<SS * QTR, 256>>>(param4);
}

// round 14
// speedup vs baseline: 1.0919x; 1.0919x over previous
#include <cuda_runtime.h>
#include <cuda_bf16.h>
#include <math.h>

// Problem constants
#define TT     1024
#define DD     4
#define PP     8
#define DPW    32                    // D*P
#define SS     256                   // N * N_SAMPLE
#define QTR    4                     // blocks per sample in P1/P3
#define NCH8   128                   // 8-step chunks per sample
#define TBL    (TT*DPW)              // 32768 table elements
#define SZ     ((size_t)SS*TT*DPW)   // 8388608 elements per output tensor
#define HLOG2PI 0.91893853320467274178f

// Scratch (static __device__ arrays — allocation-free)
__device__ float  g_mean[TBL];
__device__ float  g_sw[TBL];
__device__ float  g_amul[TT*DD];          // sigmoid(a_raw[t-1,d]), amul[0,*]=0
__device__ float  g_A8[NCH8*DD];          // per-8-chunk amul products (s-indep)
__device__ float4 g_B[SS*NCH8*8];         // per-8-chunk local end values, 4 MB
__device__ float4 g_C[SS*NCH8*8];         // exclusive carries, 4 MB

// ---------------------------------------------------------------------------
// K0: precompute per-(t,dp) tables. Fast-math; tiny.
// ---------------------------------------------------------------------------
__global__ void arma_precompute(const float* __restrict__ m,
                                const float* __restrict__ s_raw,
                                const float* __restrict__ a_raw,
                                const int*   __restrict__ dim_idx)
{
    int idx = blockIdx.x * blockDim.x + threadIdx.x;
    if (idx >= TBL) return;
    int t  = idx >> 5;
    int dp = idx & 31;
    int dd = dp >> 3;
    int p  = dp & 7;
    int src = dim_idx[dd];

    float am = 0.0f;
    if (t > 0) {
        float x = a_raw[(t - 1) * DD + src];
        am = 1.0f / (1.0f + __expf(-x));
    }

    float sv = s_raw[t * DPW + src * PP + p];
    float sw = (sv > 20.0f) ? sv : __logf(1.0f + __expf(sv));   // softplus
    float mn = (1.0f - am) * m[t * DPW + src * PP + p];

    g_mean[idx] = mn;
    g_sw[idx]   = sw;
    if (p == 0) g_amul[t * DD + dd] = am;
}

// ---------------------------------------------------------------------------
// K0b: per-8-chunk amul products (s-independent). 512 threads, trivial.
// ---------------------------------------------------------------------------
__global__ void arma_a8()
{
    int idx = threadIdx.x + blockIdx.x * blockDim.x;   // 0..511
    if (idx >= NCH8 * DD) return;
    int c  = idx >> 2;
    int dd = idx & 3;
    float a = 1.0f;
    int t0 = c << 3;
#pragma unroll
    for (int j = 0; j < 8; j++)
        a *= g_amul[((t0 + j) << 2) + dd];
    g_A8[idx] = a;
}

// ---------------------------------------------------------------------------
// P1: stream noise once (float4, DEFAULT policy so L2 retains it for P3),
// write lp (__stcs), emit TWO 8-step local summaries per 16-step chunk
// (accumulate 8, store, reset, accumulate 8, store) so the scan/carry
// granularity matches P3's LT=8. LT=16 per thread keeps 16 independent
// float4 loads in flight (DRAM latency hiding).
// Grid: 1024 blocks (s, quarter) x 128 threads (16 chunks x 8 quads).
// ---------------------------------------------------------------------------
__global__ void __launch_bounds__(128)
arma_pass1(const float4* __restrict__ noise4,
           float4* __restrict__ lp4,
           int write_lp)
{
    const int s      = blockIdx.x >> 2;
    const int qt     = blockIdx.x & 3;
    const int q      = threadIdx.x & 7;                  // dp quad
    const int chunk16= (qt << 4) + (threadIdx.x >> 3);   // 0..63
    const int dd     = q >> 1;
    const int t0     = chunk16 << 4;

    const float4* tbl_sw = (const float4*)g_sw;
    const float4* tbl_mn = (const float4*)g_mean;

    const size_t base = ((size_t)((s << 10) + t0) << 3) + q;   // float4 index

    float4 b = make_float4(0.f, 0.f, 0.f, 0.f);

#pragma unroll
    for (int i = 0; i < 16; i++) {
        const int t  = t0 + i;
        const int ti = (t << 3) + q;
        const float4 n  = noise4[base + (size_t)i * 8];        // keep in L2
        const float4 sw = tbl_sw[ti];
        const float4 mn = tbl_mn[ti];
        if (write_lp) {
            float4 lp;
            lp.x = fmaf(-0.5f * n.x, n.x, -__logf(sw.x) - HLOG2PI);
            lp.y = fmaf(-0.5f * n.y, n.y, -__logf(sw.y) - HLOG2PI);
            lp.z = fmaf(-0.5f * n.z, n.z, -__logf(sw.z) - HLOG2PI);
            lp.w = fmaf(-0.5f * n.w, n.w, -__logf(sw.w) - HLOG2PI);
            __stcs(&lp4[base + (size_t)i * 8], lp);
        }
        const float am = g_amul[(t << 2) + dd];
        b.x = fmaf(am, b.x, fmaf(sw.x, n.x, mn.x));
        b.y = fmaf(am, b.y, fmaf(sw.y, n.y, mn.y));
        b.z = fmaf(am, b.z, fmaf(sw.z, n.z, mn.z));
        b.w = fmaf(am, b.w, fmaf(sw.w, n.w, mn.w));
        if (i == 7) {
            g_B[(((size_t)s << 7) + 2 * chunk16) * 8 + q] = b;  // even 8-chunk local
            b = make_float4(0.f, 0.f, 0.f, 0.f);
        }
    }
    g_B[(((size_t)s << 7) + 2 * chunk16 + 1) * 8 + q] = b;      // odd 8-chunk local
}

// ---------------------------------------------------------------------------
// P2 (scan-lite): one 256-thread block per sample. Loads ONLY the 16KB of B
// summaries + the tiny precomputed sA8 (512 floats); warp0 runs the 128-step
// fma carry chain in smem; coalesced carry writeback. No amul table load,
// no product computation (that redundancy was 2/3 of the old scan's 6.4us).
// ---------------------------------------------------------------------------
__global__ void __launch_bounds__(256)
arma_scan()
{
    const int s   = blockIdx.x;
    const int tid = threadIdx.x;

    __shared__ float sA[NCH8][DD];        // 2 KB
    __shared__ float sB[NCH8][DPW];       // 16 KB

    // Load sA8: 512 floats = 128 float4
    if (tid < 128)
        ((float4*)sA)[tid] = ((const float4*)g_A8)[tid];

    // Load B: 128*32 floats = 1024 float4, 4 per thread
    const float4* Bs = g_B + ((size_t)s << 7) * 8;
#pragma unroll
    for (int k = 0; k < 4; k++)
        ((float4*)sB)[tid + 256 * k] = Bs[tid + 256 * k];
    __syncthreads();

    // Warp0: serial affine scan over 128 8-chunks, one dp chain per lane.
    if (tid < 32) {
        const int dp = tid;
        const int d2 = dp >> 3;
        float* Cf = (float*)g_C + ((size_t)s << 7) * 32;
        float carry = 0.0f;
#pragma unroll
        for (int c = 0; c < NCH8; c++) {
            Cf[c * 32 + dp] = carry;                       // coalesced 128B
            carry = fmaf(sA[c][d2], carry, sB[c][dp]);
        }
    }
}

// ---------------------------------------------------------------------------
// P3: replay recursion with correct 8-granular carries; noise re-read is an
// L2 hit. LT=8, grid 1024 x 256 threads = 262144 threads (~86% of chip
// thread slots — the R11 configuration that ran this pass at 12.4us).
// ---------------------------------------------------------------------------
__global__ void __launch_bounds__(256)
arma_pass2(const float4* __restrict__ noise4,
           float4* __restrict__ param4)
{
    const int s      = blockIdx.x >> 2;
    const int qt     = blockIdx.x & 3;
    const int q      = threadIdx.x & 7;
    const int chunk8 = (qt << 5) + (threadIdx.x >> 3);   // 0..127
    const int dd     = q >> 1;
    const int t0     = chunk8 << 3;

    const float4* tbl_sw = (const float4*)g_sw;
    const float4* tbl_mn = (const float4*)g_mean;

    const size_t base = ((size_t)((s << 10) + t0) << 3) + q;

    float4 pv = g_C[(((size_t)s << 7) + chunk8) * 8 + q];

#pragma unroll
    for (int i = 0; i < 8; i++) {
        const int t  = t0 + i;
        const int ti = (t << 3) + q;
        const float4 n  = noise4[base + (size_t)i * 8];   // L2 hit (read in P1)
        const float4 sw = tbl_sw[ti];
        const float4 mn = tbl_mn[ti];
        const float am  = g_amul[(t << 2) + dd];
        pv.x = fmaf(am, pv.x, fmaf(sw.x, n.x, mn.x));
        pv.y = fmaf(am, pv.y, fmaf(sw.y, n.y, mn.y));
        pv.z = fmaf(am, pv.z, fmaf(sw.z, n.z, mn.z));
        pv.w = fmaf(am, pv.w, fmaf(sw.w, n.w, mn.w));
        __stcs(&param4[base + (size_t)i * 8], pv);
    }
}

// ---------------------------------------------------------------------------
// Launch.  Inputs: 0:y 1:age 2:m 3:s_raw 4:a_raw 5:noise 6:cond_sample
//                  7:dim_idx 8:compute_log_prob
// Output: param (S,T,D,P) then log_prob (S,T,D,P), float32.
// ---------------------------------------------------------------------------
extern "C" void kernel_launch(void* const* d_in, const int* in_sizes, int n_in,
                              void* d_out, int out_size)
{
    const float* m      = (const float*)d_in[2];
    const float* s_raw  = (const float*)d_in[3];
    const float* a_raw  = (const float*)d_in[4];
    const float* noise  = (const float*)d_in[5];
    const int*   dimidx = (const int*)  d_in[7];

    float* out_param = (float*)d_out;
    int write_lp = (out_size >= (int)(2 * SZ)) ? 1 : 0;
    float* out_lp = out_param + SZ;

    const float4* noise4 = (const float4*)noise;
    float4* param4 = (float4*)out_param;
    float4* lp4    = (float4*)(write_lp ? out_lp : out_param);

    arma_precompute<<<256, 128>>>(m, s_raw, a_raw, dimidx);
    arma_a8<<<2, 256>>>();
    arma_pass1<<<SS * QTR, 128>>>(noise4, lp4, write_lp);
    arma_scan<<<SS, 256>>>();
    arma_pass2<<<SS * QTR, 256>>>(noise4, param4);
}

// round 15
// speedup vs baseline: 1.1729x; 1.0743x over previous
#include <cuda_runtime.h>
#include <cuda_bf16.h>
#include <math.h>

// Problem constants
#define TT     1024
#define DD     4
#define PP     8
#define DPW    32                    // D*P
#define SS     256                   // N * N_SAMPLE
#define LT     16                    // timesteps per chunk
#define NCHUNK 64                    // 16-chunks along T
#define QTR    4                     // blocks per sample in P1/P3
#define TBL    (TT*DPW)              // 32768 table elements
#define SZ     ((size_t)SS*TT*DPW)   // 8388608 elements per output tensor
#define HLOG2PI 0.91893853320467274178f

// Scratch (static __device__ arrays — allocation-free)
__device__ float  g_mean[TBL];
__device__ float  g_sw[TBL];
__device__ float  g_amul[TT*DD];          // sigmoid(a_raw[t-1,d]), amul[0,*]=0
__device__ float  g_A16[NCHUNK*DD];       // per-16-chunk amul products (s-indep)
__device__ float4 g_B[SS*NCHUNK*8];       // per-chunk local end values, 2 MB
__device__ float4 g_C[SS*NCHUNK*8];       // exclusive carries, 2 MB

// ---------------------------------------------------------------------------
// K0: precompute per-(t,dp) tables. Fast-math; tiny.
// ---------------------------------------------------------------------------
__global__ void arma_precompute(const float* __restrict__ m,
                                const float* __restrict__ s_raw,
                                const float* __restrict__ a_raw,
                                const int*   __restrict__ dim_idx)
{
    int idx = blockIdx.x * blockDim.x + threadIdx.x;
    if (idx >= TBL) return;
    int t  = idx >> 5;
    int dp = idx & 31;
    int dd = dp >> 3;
    int p  = dp & 7;
    int src = dim_idx[dd];

    float am = 0.0f;
    if (t > 0) {
        float x = a_raw[(t - 1) * DD + src];
        am = 1.0f / (1.0f + __expf(-x));
    }

    float sv = s_raw[t * DPW + src * PP + p];
    float sw = (sv > 20.0f) ? sv : __logf(1.0f + __expf(sv));   // softplus
    float mn = (1.0f - am) * m[t * DPW + src * PP + p];

    g_mean[idx] = mn;
    g_sw[idx]   = sw;
    if (p == 0) g_amul[t * DD + dd] = am;
}

// ---------------------------------------------------------------------------
// K0b: per-16-chunk amul products (s-independent). 256 threads, trivial.
// Removes this redundant work from all 256 scan blocks.
// ---------------------------------------------------------------------------
__global__ void arma_a16()
{
    int idx = threadIdx.x;               // 0..255
    if (idx >= NCHUNK * DD) return;
    int c  = idx >> 2;
    int dd = idx & 3;
    float a = 1.0f;
    int t0 = c << 4;
#pragma unroll
    for (int j = 0; j < LT; j++)
        a *= g_amul[((t0 + j) << 2) + dd];
    g_A16[idx] = a;
}

// ---------------------------------------------------------------------------
// P1: stream noise once (float4, DEFAULT policy so L2 retains it for P3),
// write lp (__stcs, never re-read), emit one per-16-chunk summary b.
// Grid: 1024 blocks (s, quarter) x 128 threads (16 chunks x 8 quads, LT=16
// keeps 16 independent float4 loads in flight for DRAM latency hiding).
// ---------------------------------------------------------------------------
__global__ void __launch_bounds__(128)
arma_pass1(const float4* __restrict__ noise4,
           float4* __restrict__ lp4,
           int write_lp)
{
    const int s     = blockIdx.x >> 2;
    const int qt    = blockIdx.x & 3;
    const int q     = threadIdx.x & 7;                  // dp quad: dp = 4q..4q+3
    const int chunk = (qt << 4) + (threadIdx.x >> 3);   // 0..63
    const int dd    = q >> 1;
    const int t0    = chunk << 4;

    const float4* tbl_sw = (const float4*)g_sw;
    const float4* tbl_mn = (const float4*)g_mean;

    const size_t base = ((size_t)((s << 10) + t0) << 3) + q;   // float4 index

    float4 b = make_float4(0.f, 0.f, 0.f, 0.f);

#pragma unroll
    for (int i = 0; i < LT; i++) {
        const int t  = t0 + i;
        const int ti = (t << 3) + q;
        const float4 n = noise4[base + (size_t)i * 8];         // keep in L2
        const float4 sw = tbl_sw[ti];
        const float4 mn = tbl_mn[ti];
        if (write_lp) {
            float4 lp;
            lp.x = fmaf(-0.5f * n.x, n.x, -__logf(sw.x) - HLOG2PI);
            lp.y = fmaf(-0.5f * n.y, n.y, -__logf(sw.y) - HLOG2PI);
            lp.z = fmaf(-0.5f * n.z, n.z, -__logf(sw.z) - HLOG2PI);
            lp.w = fmaf(-0.5f * n.w, n.w, -__logf(sw.w) - HLOG2PI);
            __stcs(&lp4[base + (size_t)i * 8], lp);
        }
        const float am = g_amul[(t << 2) + dd];
        b.x = fmaf(am, b.x, fmaf(sw.x, n.x, mn.x));
        b.y = fmaf(am, b.y, fmaf(sw.y, n.y, mn.y));
        b.z = fmaf(am, b.z, fmaf(sw.z, n.z, mn.z));
        b.w = fmaf(am, b.w, fmaf(sw.w, n.w, mn.w));
    }
    g_B[(((size_t)s << 6) + chunk) * 8 + q] = b;
}

// ---------------------------------------------------------------------------
// P2 (scan-lite): one 256-thread block per sample. Loads ONLY 8KB of B
// summaries + the tiny precomputed A16 (256 floats); warp0 runs the 64-step
// fma carry chain in smem; coalesced carry writeback.
// ---------------------------------------------------------------------------
__global__ void __launch_bounds__(256)
arma_scan()
{
    const int s   = blockIdx.x;
    const int tid = threadIdx.x;

    __shared__ float sA[NCHUNK][DD];      // 1 KB
    __shared__ float sB[NCHUNK][DPW];     // 8 KB

    // Load A16: 256 floats = 64 float4
    if (tid < 64)
        ((float4*)sA)[tid] = ((const float4*)g_A16)[tid];

    // Load B: 512 float4, 2 per thread
    const float4* Bs = g_B + ((size_t)s << 6) * 8;
    ((float4*)sB)[tid]       = Bs[tid];
    ((float4*)sB)[tid + 256] = Bs[tid + 256];
    __syncthreads();

    // Warp0: serial affine scan over 64 chunks, one dp chain per lane.
    if (tid < 32) {
        const int dp = tid;
        const int d2 = dp >> 3;
        float* Cf = (float*)g_C + ((size_t)s << 6) * 32;
        float carry = 0.0f;
#pragma unroll
        for (int c = 0; c < NCHUNK; c++) {
            Cf[c * 32 + dp] = carry;                       // coalesced 128B
            carry = fmaf(sA[c][d2], carry, sB[c][dp]);
        }
    }
}

// ---------------------------------------------------------------------------
// P3: replay recursion with correct carries; noise re-read is an L2 hit.
// Grid: 1024 blocks x 128 threads, LT=16 (R10/R12-equivalent shape).
// ---------------------------------------------------------------------------
__global__ void __launch_bounds__(128)
arma_pass2(const float4* __restrict__ noise4,
           float4* __restrict__ param4)
{
    const int s     = blockIdx.x >> 2;
    const int qt    = blockIdx.x & 3;
    const int q     = threadIdx.x & 7;
    const int chunk = (qt << 4) + (threadIdx.x >> 3);
    const int dd    = q >> 1;
    const int t0    = chunk << 4;

    const float4* tbl_sw = (const float4*)g_sw;
    const float4* tbl_mn = (const float4*)g_mean;

    const size_t base = ((size_t)((s << 10) + t0) << 3) + q;

    float4 pv = g_C[(((size_t)s << 6) + chunk) * 8 + q];

#pragma unroll
    for (int i = 0; i < LT; i++) {
        const int t  = t0 + i;
        const int ti = (t << 3) + q;
        const float4 n  = noise4[base + (size_t)i * 8];   // L2 hit (read in P1)
        const float4 sw = tbl_sw[ti];
        const float4 mn = tbl_mn[ti];
        const float am  = g_amul[(t << 2) + dd];
        pv.x = fmaf(am, pv.x, fmaf(sw.x, n.x, mn.x));
        pv.y = fmaf(am, pv.y, fmaf(sw.y, n.y, mn.y));
        pv.z = fmaf(am, pv.z, fmaf(sw.z, n.z, mn.z));
        pv.w = fmaf(am, pv.w, fmaf(sw.w, n.w, mn.w));
        __stcs(&param4[base + (size_t)i * 8], pv);
    }
}

// ---------------------------------------------------------------------------
// Launch.  Inputs: 0:y 1:age 2:m 3:s_raw 4:a_raw 5:noise 6:cond_sample
//                  7:dim_idx 8:compute_log_prob
// Output: param (S,T,D,P) then log_prob (S,T,D,P), float32.
// ---------------------------------------------------------------------------
extern "C" void kernel_launch(void* const* d_in, const int* in_sizes, int n_in,
                              void* d_out, int out_size)
{
    const float* m      = (const float*)d_in[2];
    const float* s_raw  = (const float*)d_in[3];
    const float* a_raw  = (const float*)d_in[4];
    const float* noise  = (const float*)d_in[5];
    const int*   dimidx = (const int*)  d_in[7];

    float* out_param = (float*)d_out;
    int write_lp = (out_size >= (int)(2 * SZ)) ? 1 : 0;
    float* out_lp = out_param + SZ;

    const float4* noise4 = (const float4*)noise;
    float4* param4 = (float4*)out_param;
    float4* lp4    = (float4*)(write_lp ? out_lp : out_param);

    arma_precompute<<<256, 128>>>(m, s_raw, a_raw, dimidx);
    arma_a16<<<1, 256>>>();
    arma_pass1<<<SS * QTR, 128>>>(noise4, lp4, write_lp);
    arma_scan<<<SS, 256>>>();
    arma_pass2<<<SS * QTR, 128>>>(noise4, param4);
}

// round 16
// speedup vs baseline: 1.2656x; 1.0790x over previous
#include <cuda_runtime.h>
#include <cuda_bf16.h>
#include <math.h>

// Problem constants
#define TT     1024
#define DD     4
#define PP     8
#define DPW    32                    // D*P
#define SS     256                   // N * N_SAMPLE
#define LT     16                    // timesteps per chunk
#define NCHUNK 64                    // 16-chunks along T
#define QTR    4                     // blocks per sample in P1/P3
#define TBL    (TT*DPW)              // 32768 table elements
#define SZ     ((size_t)SS*TT*DPW)   // 8388608 elements per output tensor
#define HLOG2PI 0.91893853320467274178f

// Scratch (static __device__ arrays — allocation-free)
__device__ float  g_mean[TBL];
__device__ float  g_sw[TBL];
__device__ float  g_amul[TT*DD];          // sigmoid(a_raw[t-1,d]), amul[0,*]=0
__device__ float  g_A16[NCHUNK*DD];       // per-16-chunk amul products (s-indep)
__device__ float4 g_B[SS*NCHUNK*8];       // per-chunk local end values, 2 MB

// ---------------------------------------------------------------------------
// K0: precompute per-(t,dp) tables. Fast-math; tiny.
// ---------------------------------------------------------------------------
__global__ void arma_precompute(const float* __restrict__ m,
                                const float* __restrict__ s_raw,
                                const float* __restrict__ a_raw,
                                const int*   __restrict__ dim_idx)
{
    int idx = blockIdx.x * blockDim.x + threadIdx.x;
    if (idx >= TBL) return;
    int t  = idx >> 5;
    int dp = idx & 31;
    int dd = dp >> 3;
    int p  = dp & 7;
    int src = dim_idx[dd];

    float am = 0.0f;
    if (t > 0) {
        float x = a_raw[(t - 1) * DD + src];
        am = 1.0f / (1.0f + __expf(-x));
    }

    float sv = s_raw[t * DPW + src * PP + p];
    float sw = (sv > 20.0f) ? sv : __logf(1.0f + __expf(sv));   // softplus
    float mn = (1.0f - am) * m[t * DPW + src * PP + p];

    g_mean[idx] = mn;
    g_sw[idx]   = sw;
    if (p == 0) g_amul[t * DD + dd] = am;
}

// ---------------------------------------------------------------------------
// K0b: per-16-chunk amul products (s-independent). 256 threads, trivial.
// ---------------------------------------------------------------------------
__global__ void arma_a16()
{
    int idx = threadIdx.x;               // 0..255
    if (idx >= NCHUNK * DD) return;
    int c  = idx >> 2;
    int dd = idx & 3;
    float a = 1.0f;
    int t0 = c << 4;
#pragma unroll
    for (int j = 0; j < LT; j++)
        a *= g_amul[((t0 + j) << 2) + dd];
    g_A16[idx] = a;
}

// ---------------------------------------------------------------------------
// P1: stream noise once (float4, DEFAULT policy so L2 retains it for P3),
// write lp (__stcs, never re-read), emit one per-16-chunk summary b.
// Grid: 1024 blocks (s, quarter) x 128 threads (16 chunks x 8 quads, LT=16
// keeps 16 independent float4 loads in flight for DRAM latency hiding).
// ---------------------------------------------------------------------------
__global__ void __launch_bounds__(128)
arma_pass1(const float4* __restrict__ noise4,
           float4* __restrict__ lp4,
           int write_lp)
{
    const int s     = blockIdx.x >> 2;
    const int qt    = blockIdx.x & 3;
    const int q     = threadIdx.x & 7;                  // dp quad: dp = 4q..4q+3
    const int chunk = (qt << 4) + (threadIdx.x >> 3);   // 0..63
    const int dd    = q >> 1;
    const int t0    = chunk << 4;

    const float4* tbl_sw = (const float4*)g_sw;
    const float4* tbl_mn = (const float4*)g_mean;

    const size_t base = ((size_t)((s << 10) + t0) << 3) + q;   // float4 index

    float4 b = make_float4(0.f, 0.f, 0.f, 0.f);

#pragma unroll
    for (int i = 0; i < LT; i++) {
        const int t  = t0 + i;
        const int ti = (t << 3) + q;
        const float4 n = noise4[base + (size_t)i * 8];         // keep in L2
        const float4 sw = tbl_sw[ti];
        const float4 mn = tbl_mn[ti];
        if (write_lp) {
            float4 lp;
            lp.x = fmaf(-0.5f * n.x, n.x, -__logf(sw.x) - HLOG2PI);
            lp.y = fmaf(-0.5f * n.y, n.y, -__logf(sw.y) - HLOG2PI);
            lp.z = fmaf(-0.5f * n.z, n.z, -__logf(sw.z) - HLOG2PI);
            lp.w = fmaf(-0.5f * n.w, n.w, -__logf(sw.w) - HLOG2PI);
            __stcs(&lp4[base + (size_t)i * 8], lp);
        }
        const float am = g_amul[(t << 2) + dd];
        b.x = fmaf(am, b.x, fmaf(sw.x, n.x, mn.x));
        b.y = fmaf(am, b.y, fmaf(sw.y, n.y, mn.y));
        b.z = fmaf(am, b.z, fmaf(sw.z, n.z, mn.z));
        b.w = fmaf(am, b.w, fmaf(sw.w, n.w, mn.w));
    }
    g_B[(((size_t)s << 6) + chunk) * 8 + q] = b;
}

// ---------------------------------------------------------------------------
// P3 (scan folded in): grid 1024 (s, quarter) x 128 threads.
// Prologue: load the sample's full B (8KB, L2-hot from P1) + A16 (1KB);
// warp0 runs the 64-step fma carry chain in smem (~300cyc, redundant x4 per
// sample but far cheaper than a dedicated 5.4us kernel + g_C round trip),
// keeping carries only for this block's 16 chunks.
// Main: replay recursion; noise re-read is an L2 hit.
// ---------------------------------------------------------------------------
__global__ void __launch_bounds__(128)
arma_pass2(const float4* __restrict__ noise4,
           float4* __restrict__ param4)
{
    const int s     = blockIdx.x >> 2;
    const int qt    = blockIdx.x & 3;
    const int tid   = threadIdx.x;
    const int q     = tid & 7;
    const int lchunk= tid >> 3;                         // 0..15 local chunk
    const int chunk = (qt << 4) + lchunk;               // 0..63 global chunk
    const int dd    = q >> 1;
    const int t0    = chunk << 4;

    __shared__ float sA[NCHUNK][DD];      // 1 KB   per-chunk amul products
    __shared__ float sB[NCHUNK][DPW];     // 8 KB   per-chunk local end values
    __shared__ float sC[16][DPW];         // 2 KB   carries for local chunks

    // Load A16 (64 float4) and B (512 float4, 4 per thread)
    if (tid < 64)
        ((float4*)sA)[tid] = ((const float4*)g_A16)[tid];
    const float4* Bs = g_B + ((size_t)s << 6) * 8;
#pragma unroll
    for (int k = 0; k < 4; k++)
        ((float4*)sB)[tid + 128 * k] = Bs[tid + 128 * k];
    __syncthreads();

    // Warp0: serial affine scan; keep carries for this block's chunk range.
    if (tid < 32) {
        const int dp = tid;
        const int d2 = dp >> 3;
        const int lo = qt << 4;
        float carry = 0.0f;
#pragma unroll
        for (int c = 0; c < NCHUNK; c++) {
            if ((c >> 4) == qt) sC[c - lo][dp] = carry;
            carry = fmaf(sA[c][d2], carry, sB[c][dp]);
        }
    }
    __syncthreads();

    const float4* tbl_sw = (const float4*)g_sw;
    const float4* tbl_mn = (const float4*)g_mean;

    const size_t base = ((size_t)((s << 10) + t0) << 3) + q;

    float4 pv = ((const float4*)sC[lchunk])[q];

#pragma unroll
    for (int i = 0; i < LT; i++) {
        const int t  = t0 + i;
        const int ti = (t << 3) + q;
        const float4 n  = noise4[base + (size_t)i * 8];   // L2 hit (read in P1)
        const float4 sw = tbl_sw[ti];
        const float4 mn = tbl_mn[ti];
        const float am  = g_amul[(t << 2) + dd];
        pv.x = fmaf(am, pv.x, fmaf(sw.x, n.x, mn.x));
        pv.y = fmaf(am, pv.y, fmaf(sw.y, n.y, mn.y));
        pv.z = fmaf(am, pv.z, fmaf(sw.z, n.z, mn.z));
        pv.w = fmaf(am, pv.w, fmaf(sw.w, n.w, mn.w));
        __stcs(&param4[base + (size_t)i * 8], pv);
    }
}

// ---------------------------------------------------------------------------
// Launch.  Inputs: 0:y 1:age 2:m 3:s_raw 4:a_raw 5:noise 6:cond_sample
//                  7:dim_idx 8:compute_log_prob
// Output: param (S,T,D,P) then log_prob (S,T,D,P), float32.
// ---------------------------------------------------------------------------
extern "C" void kernel_launch(void* const* d_in, const int* in_sizes, int n_in,
                              void* d_out, int out_size)
{
    const float* m      = (const float*)d_in[2];
    const float* s_raw  = (const float*)d_in[3];
    const float* a_raw  = (const float*)d_in[4];
    const float* noise  = (const float*)d_in[5];
    const int*   dimidx = (const int*)  d_in[7];

    float* out_param = (float*)d_out;
    int write_lp = (out_size >= (int)(2 * SZ)) ? 1 : 0;
    float* out_lp = out_param + SZ;

    const float4* noise4 = (const float4*)noise;
    float4* param4 = (float4*)out_param;
    float4* lp4    = (float4*)(write_lp ? out_lp : out_param);

    arma_precompute<<<256, 128>>>(m, s_raw, a_raw, dimidx);
    arma_a16<<<1, 256>>>();
    arma_pass1<<<SS * QTR, 128>>>(noise4, lp4, write_lp);
    arma_pass2<<<SS * QTR, 128>>>(noise4, param4);
}